// round 4
// baseline (speedup 1.0000x reference)
#include <cuda_runtime.h>
#include <stdint.h>

static constexpr int Dk   = 4096;
static constexpr int Oo   = 4096;
static constexpr int Kmid = 128;
static constexpr int NTOK = 8192;
static constexpr int NK1  = 128;      // K-tiles in kernel 1 (4096/32)

// Scratch (device globals — no allocation allowed)
__device__ float g_wlow[NTOK * Kmid];   // 4 MB  tf32-rounded, score-weighted low acts
__device__ float g_Aw[136 * Dk];        // 2.2MB tf32-rounded [A(128 rows) ; Wr(8 rows)]
__device__ float g_Bt2[Oo * Kmid];      // 2 MB  tf32-rounded Bt2[o][h*16+rr]

// ---------------------------------------------------------------------------
// helpers
// ---------------------------------------------------------------------------
__device__ __forceinline__ float tf32r(float x) {
    uint32_t u; asm("cvt.rna.tf32.f32 %0, %1;" : "=r"(u) : "f"(x));
    return __uint_as_float(u);
}
__device__ __forceinline__ float4 tf32r4(float4 v) {
    return make_float4(tf32r(v.x), tf32r(v.y), tf32r(v.z), tf32r(v.w));
}
__device__ __forceinline__ void mma8(float* c, uint32_t a0, uint32_t a1,
                                     uint32_t a2, uint32_t a3,
                                     uint32_t b0, uint32_t b1) {
    asm volatile(
        "mma.sync.aligned.m16n8k8.row.col.f32.tf32.tf32.f32 "
        "{%0,%1,%2,%3}, {%4,%5,%6,%7}, {%8,%9}, {%0,%1,%2,%3};\n"
        : "+f"(c[0]), "+f"(c[1]), "+f"(c[2]), "+f"(c[3])
        : "r"(a0), "r"(a1), "r"(a2), "r"(a3), "r"(b0), "r"(b1));
}
#define CP16(dst_u32, src_ptr) \
    asm volatile("cp.async.cg.shared.global [%0], [%1], 16;\n" :: "r"(dst_u32), "l"(src_ptr))
#define CP_COMMIT() asm volatile("cp.async.commit_group;\n" ::: "memory")
#define CP_WAIT(N)  asm volatile("cp.async.wait_group %0;\n" :: "n"(N) : "memory")

static constexpr int LD = 36;   // padded row stride (floats): (4r+cc)%32 distinct -> no conflicts

// ---------------------------------------------------------------------------
// Kernel 0: pre-round weights into scratch
// ---------------------------------------------------------------------------
__global__ void prep(const float* __restrict__ A, const float* __restrict__ Wr,
                     const float* __restrict__ Bm) {
    int idx = blockIdx.x * 256 + threadIdx.x;
    if (idx < 136 * Dk) {
        int row = idx >> 12, col = idx & (Dk - 1);
        float v = (row < 128) ? A[(size_t)row * Dk + col]
                              : Wr[(size_t)(row - 128) * Dk + col];
        g_Aw[idx] = tf32r(v);
    }
    if (idx < Oo * Kmid) {
        int o = idx >> 7, k = idx & 127;
        g_Bt2[idx] = tf32r(Bm[((size_t)((k >> 4) * Oo + o)) * 16 + (k & 15)]);
    }
}

// ---------------------------------------------------------------------------
// Kernel 1: low = x @ [A;Wr]^T  (BM=64, BN=128 + 8 router, BK=32), softmax,
//           wlow = low * 16*softmax   — tf32 mma.sync, cp.async weight ring
// SMEM: slog@0(2K) ssc@2K(2K) xs@4K (2 x 64*36*4=9216) ws@22528 (3 x 136*36*4=19584)
// ---------------------------------------------------------------------------
static constexpr int K1_SMEM = 22528 + 3 * 19584;   // 81280

__global__ __launch_bounds__(256, 1)
void k1_low(const float* __restrict__ x, const float* __restrict__ br) {
    extern __shared__ char sm[];
    const uint32_t su = (uint32_t)__cvta_generic_to_shared(sm);
    float* slog = (float*)(sm);
    float* ssc  = (float*)(sm + 2048);
    float* xs0  = (float*)(sm + 4096);
    float* ws0  = (float*)(sm + 22528);

    const int tid = threadIdx.x, wid = tid >> 5, lane = tid & 31;
    const int wm = wid & 1;            // row half  (32 rows)
    const int wn = wid >> 1;           // col quarter (32 cols)
    const int r = lane >> 2, cc = lane & 3;
    const int tok0 = blockIdx.x * 64;
    const bool do_r = (wn == 0);

    float acc[2][4][4] = {};
    float racc[2][4]   = {};
    float4 rx[2][2];

    auto ldgx = [&](int kt, int b) {
        const float* xp = x + (size_t)tok0 * Dk + kt * 32;
#pragma unroll
        for (int p = 0; p < 2; p++) {
            int i = tid + p * 256, row = i >> 3, q = i & 7;
            rx[b][p] = *reinterpret_cast<const float4*>(xp + (size_t)row * Dk + q * 4);
        }
    };
    auto stsx = [&](int b, int st) {
        float* xb = xs0 + st * (64 * LD);
#pragma unroll
        for (int p = 0; p < 2; p++) {
            int i = tid + p * 256, row = i >> 3, q = i & 7;
            *reinterpret_cast<float4*>(&xb[row * LD + q * 4]) = tf32r4(rx[b][p]);
        }
    };
    auto cpws = [&](int kt, int st) {
        const float* wp = g_Aw + kt * 32;
        uint32_t wb = su + 22528 + st * 19584;
#pragma unroll
        for (int p = 0; p < 5; p++) {
            int i = tid + p * 256;
            if (i < 1088) {
                int row = i >> 3, q = i & 7;
                CP16(wb + (row * LD + q * 4) * 4, wp + (size_t)row * Dk + q * 4);
            }
        }
    };

    // prologue
    ldgx(0, 0);
    stsx(0, 0);
    ldgx(1, 1);
    cpws(0, 0); CP_COMMIT();
    cpws(1, 1); CP_COMMIT();

    for (int kt = 0; kt < NK1; kt++) {
        CP_WAIT(1);            // weight group for tile kt retired
        __syncthreads();       // publishes cp.async + previous stsx; protects reuse

        if (kt + 1 < NK1) stsx((kt + 1) & 1, (kt + 1) & 1);
        if (kt + 2 < NK1) { cpws(kt + 2, (kt + 2) % 3); ldgx(kt + 2, kt & 1); }
        CP_COMMIT();           // always commit (possibly empty) to keep accounting

        const float* xb = xs0 + (kt & 1) * (64 * LD);
        const float* wb = ws0 + (kt % 3) * (136 * LD);
        const uint32_t* xu = reinterpret_cast<const uint32_t*>(xb);
        const uint32_t* wu = reinterpret_cast<const uint32_t*>(wb);
#pragma unroll
        for (int ks = 0; ks < 4; ks++) {
            const int k0 = ks * 8;
            uint32_t a[2][4];
#pragma unroll
            for (int mt = 0; mt < 2; mt++) {
                int base = (wm * 32 + mt * 16 + r) * LD + k0 + cc;
                a[mt][0] = xu[base];
                a[mt][1] = xu[base + 8 * LD];
                a[mt][2] = xu[base + 4];
                a[mt][3] = xu[base + 8 * LD + 4];
            }
#pragma unroll
            for (int nt = 0; nt < 4; nt++) {
                int nb = (wn * 32 + nt * 8 + r) * LD + k0 + cc;
                uint32_t b0 = wu[nb], b1 = wu[nb + 4];
                mma8(acc[0][nt], a[0][0], a[0][1], a[0][2], a[0][3], b0, b1);
                mma8(acc[1][nt], a[1][0], a[1][1], a[1][2], a[1][3], b0, b1);
            }
            if (do_r) {
                int nb = (128 + r) * LD + k0 + cc;
                uint32_t b0 = wu[nb], b1 = wu[nb + 4];
                mma8(racc[0], a[0][0], a[0][1], a[0][2], a[0][3], b0, b1);
                mma8(racc[1], a[1][0], a[1][1], a[1][2], a[1][3], b0, b1);
            }
        }
    }

    // router logits -> slog
    if (do_r) {
#pragma unroll
        for (int mt = 0; mt < 2; mt++) {
            int tr = wm * 32 + mt * 16 + r;
            slog[tr * 8 + 2 * cc]           = racc[mt][0];
            slog[tr * 8 + 2 * cc + 1]       = racc[mt][1];
            slog[(tr + 8) * 8 + 2 * cc]     = racc[mt][2];
            slog[(tr + 8) * 8 + 2 * cc + 1] = racc[mt][3];
        }
    }
    __syncthreads();
    if (tid < 64) {   // softmax over 8 heads, fold H*SCALING = 16
        float l[8], m = -1e30f;
#pragma unroll
        for (int h = 0; h < 8; h++) {
            l[h] = slog[tid * 8 + h] + br[h];
            m = fmaxf(m, l[h]);
        }
        float s = 0.0f;
#pragma unroll
        for (int h = 0; h < 8; h++) { l[h] = __expf(l[h] - m); s += l[h]; }
        float inv = 16.0f / s;
#pragma unroll
        for (int h = 0; h < 8; h++) ssc[tid * 8 + h] = l[h] * inv;
    }
    __syncthreads();

    // scale + store wlow (tf32-rounded)
#pragma unroll
    for (int mt = 0; mt < 2; mt++) {
        int tr = wm * 32 + mt * 16 + r;
#pragma unroll
        for (int nt = 0; nt < 4; nt++) {
            int col  = wn * 32 + nt * 8 + 2 * cc;
            int head = (wn * 32 + nt * 8) >> 4;
            float s0 = ssc[tr * 8 + head];
            float s1 = ssc[(tr + 8) * 8 + head];
            *reinterpret_cast<float2*>(&g_wlow[(size_t)(tok0 + tr) * Kmid + col]) =
                make_float2(tf32r(acc[mt][nt][0] * s0), tf32r(acc[mt][nt][1] * s0));
            *reinterpret_cast<float2*>(&g_wlow[(size_t)(tok0 + tr + 8) * Kmid + col]) =
                make_float2(tf32r(acc[mt][nt][2] * s1), tf32r(acc[mt][nt][3] * s1));
        }
    }
}

// ---------------------------------------------------------------------------
// Kernel 2: out = wlow[8192,128] @ Bt2[4096,128]^T  — persistent 148 CTAs
// Full K=128 resident. A tile per m-block (4 chunks x 128x36), B double-buffered.
// SMEM: A @0 (4*18432=73728), B @73728 (2 x 73728)
// ---------------------------------------------------------------------------
static constexpr int CHB     = 128 * LD * 4;          // 18432 bytes per chunk
static constexpr int K2_SMEM = 3 * 4 * CHB;           // 221184
static constexpr int NTILES  = (NTOK / 128) * (Oo / 128);   // 2048
static constexpr int GRID2   = 148;

__global__ __launch_bounds__(256, 1)
void k2_up(float* __restrict__ out) {
    extern __shared__ char sm[];
    const uint32_t su = (uint32_t)__cvta_generic_to_shared(sm);
    const int tid = threadIdx.x, wid = tid >> 5, lane = tid & 31;
    const int nw = wid & 1;            // col half  (64)
    const int mw = wid >> 1;           // row quarter (32)
    const int r = lane >> 2, cc = lane & 3;

    // copy one 128x128 f32 tile (row stride Kmid) into 4 padded chunks
    auto cp_tile = [&](const float* src, uint32_t dst_off) {
#pragma unroll
        for (int p = 0; p < 16; p++) {
            int i = tid + p * 256;
            int row = i >> 5, j = i & 31, ch = j >> 3, q = j & 7;
            CP16(su + dst_off + ch * CHB + (row * LD + q * 4) * 4,
                 src + (size_t)row * Kmid + j * 4);
        }
    };

    const int t0 = (blockIdx.x * NTILES) / GRID2;
    const int t1 = ((blockIdx.x + 1) * NTILES) / GRID2;
    int buf = 0, curmb = -1;

    for (int t = t0; t < t1; t++) {
        const int mb = t >> 5, nt = t & 31;
        const int m0 = mb * 128, nb = nt * 128;

        if (mb != curmb) {
            cp_tile(g_wlow + (size_t)m0 * Kmid, 0);
            buf = 0;
            cp_tile(g_Bt2 + (size_t)nb * Kmid, (uint32_t)(4 * CHB));
            CP_COMMIT();
            curmb = mb;
        }
        CP_WAIT(0);
        __syncthreads();     // current A + B(buf) visible; prior reads of buf^1 done

        const bool nextsame = (t + 1 < t1) && (((t + 1) >> 5) == mb);
        if (nextsame) {      // prefetch next B overlaps compute + epilogue
            cp_tile(g_Bt2 + (size_t)((nt + 1) * 128) * Kmid,
                    (uint32_t)(4 * CHB + (buf ^ 1) * 4 * CHB));
            CP_COMMIT();
        }

        float acc[2][8][4] = {};
        const float* as = (const float*)sm;
        const float* bs = (const float*)(sm + 4 * CHB + buf * 4 * CHB);
#pragma unroll
        for (int ch = 0; ch < 4; ch++) {
            const uint32_t* au = reinterpret_cast<const uint32_t*>(as + ch * (128 * LD));
            const uint32_t* bu = reinterpret_cast<const uint32_t*>(bs + ch * (128 * LD));
#pragma unroll
            for (int ks = 0; ks < 4; ks++) {
                const int k0 = ks * 8;
                uint32_t a[2][4];
#pragma unroll
                for (int mt = 0; mt < 2; mt++) {
                    int base = (mw * 32 + mt * 16 + r) * LD + k0 + cc;
                    a[mt][0] = au[base];
                    a[mt][1] = au[base + 8 * LD];
                    a[mt][2] = au[base + 4];
                    a[mt][3] = au[base + 8 * LD + 4];
                }
#pragma unroll
                for (int j = 0; j < 8; j++) {
                    int nbx = (nw * 64 + j * 8 + r) * LD + k0 + cc;
                    uint32_t b0 = bu[nbx], b1 = bu[nbx + 4];
                    mma8(acc[0][j], a[0][0], a[0][1], a[0][2], a[0][3], b0, b1);
                    mma8(acc[1][j], a[1][0], a[1][1], a[1][2], a[1][3], b0, b1);
                }
            }
        }

        // epilogue: STG (overlaps with in-flight prefetch)
#pragma unroll
        for (int mt = 0; mt < 2; mt++) {
            int row = m0 + mw * 32 + mt * 16 + r;
#pragma unroll
            for (int j = 0; j < 8; j++) {
                int col = nb + nw * 64 + j * 8 + 2 * cc;
                *reinterpret_cast<float2*>(&out[(size_t)row * Oo + col]) =
                    make_float2(acc[mt][j][0], acc[mt][j][1]);
                *reinterpret_cast<float2*>(&out[(size_t)(row + 8) * Oo + col]) =
                    make_float2(acc[mt][j][2], acc[mt][j][3]);
            }
        }
        if (nextsame) buf ^= 1;
    }
}

// ---------------------------------------------------------------------------
extern "C" void kernel_launch(void* const* d_in, const int* in_sizes, int n_in,
                              void* d_out, int out_size) {
    const float* x  = (const float*)d_in[0];
    const float* A  = (const float*)d_in[1];
    const float* Bm = (const float*)d_in[2];
    const float* Wr = (const float*)d_in[3];
    const float* br = (const float*)d_in[4];
    float* out = (float*)d_out;

    cudaFuncSetAttribute(k1_low, cudaFuncAttributeMaxDynamicSharedMemorySize, K1_SMEM);
    cudaFuncSetAttribute(k2_up,  cudaFuncAttributeMaxDynamicSharedMemorySize, K2_SMEM);

    prep<<<(136 * Dk + 255) / 256, 256>>>(A, Wr, Bm);
    k1_low<<<NTOK / 64, 256, K1_SMEM>>>(x, br);
    k2_up<<<GRID2, 256, K2_SMEM>>>(out);
}

// round 6
// speedup vs baseline: 1.6329x; 1.6329x over previous
#include <cuda_runtime.h>
#include <cuda_fp16.h>
#include <stdint.h>

static constexpr int Dk   = 4096;
static constexpr int Oo   = 4096;
static constexpr int Kmid = 128;
static constexpr int NTOK = 8192;
static constexpr int NK1  = 64;       // K-tiles in kernel 1 (4096/64)

// Scratch (device globals — no allocation allowed)
__device__ __half g_wlowh[NTOK * Kmid];   // 2 MB   score-weighted low acts (fp16)
__device__ __half g_Awh[136 * Dk];        // 1.1 MB [A(128 rows) ; Wr(8 rows)] fp16
__device__ __half g_Bth[Oo * Kmid];       // 1 MB   Bt[o][h*16+rr] fp16

// ---------------------------------------------------------------------------
// helpers
// ---------------------------------------------------------------------------
__device__ __forceinline__ void mma16(float* c, uint32_t a0, uint32_t a1,
                                      uint32_t a2, uint32_t a3,
                                      uint32_t b0, uint32_t b1) {
    asm volatile(
        "mma.sync.aligned.m16n8k16.row.col.f32.f16.f16.f32 "
        "{%0,%1,%2,%3}, {%4,%5,%6,%7}, {%8,%9}, {%0,%1,%2,%3};\n"
        : "+f"(c[0]), "+f"(c[1]), "+f"(c[2]), "+f"(c[3])
        : "r"(a0), "r"(a1), "r"(a2), "r"(a3), "r"(b0), "r"(b1));
}
#define CP16(dst_u32, src_ptr) \
    asm volatile("cp.async.cg.shared.global [%0], [%1], 16;\n" :: "r"(dst_u32), "l"(src_ptr))
#define CP_COMMIT() asm volatile("cp.async.commit_group;\n" ::: "memory")
#define CP_WAIT(N)  asm volatile("cp.async.wait_group %0;\n" :: "n"(N) : "memory")

static constexpr int S1 = 36;   // k1 row stride in words (144B): 36%32==4 -> conflict-free
static constexpr int S2 = 68;   // k2 row stride in words (272B): 68%32==4 -> conflict-free

// ---------------------------------------------------------------------------
// Kernel 0: convert weights to fp16 scratch
// ---------------------------------------------------------------------------
__global__ void prep(const float* __restrict__ A, const float* __restrict__ Wr,
                     const float* __restrict__ Bm) {
    int idx = blockIdx.x * 256 + threadIdx.x;
    if (idx < 136 * Dk) {
        int row = idx >> 12, col = idx & (Dk - 1);
        float v = (row < 128) ? A[(size_t)row * Dk + col]
                              : Wr[(size_t)(row - 128) * Dk + col];
        g_Awh[idx] = __float2half_rn(v);
    }
    if (idx < Oo * Kmid) {
        int o = idx >> 7, k = idx & 127;
        g_Bth[idx] = __float2half_rn(
            Bm[((size_t)((k >> 4) * Oo + o)) * 16 + (k & 15)]);
    }
}

// ---------------------------------------------------------------------------
// Kernel 1: low = x @ [A;Wr]^T  (BM=64, BN=128 + 8 router, BK=64 halves),
//           softmax over heads, wlow = low * 16*softmax   — fp16 mma.sync
// SMEM: slog@0(2K) ssc@2K(2K) xs@4096 (2 x 64*144=9216) ws@22528 (3 x 136*144=19584)
// ---------------------------------------------------------------------------
static constexpr int K1_SMEM = 22528 + 3 * 19584;   // 81280

__global__ __launch_bounds__(256, 1)
void k1_low(const float* __restrict__ x, const float* __restrict__ br) {
    extern __shared__ char sm[];
    const uint32_t su = (uint32_t)__cvta_generic_to_shared(sm);
    float* slog = (float*)(sm);
    float* ssc  = (float*)(sm + 2048);
    char*  xs0  = sm + 4096;
    char*  ws0  = sm + 22528;

    const int tid = threadIdx.x, wid = tid >> 5, lane = tid & 31;
    const int wm = wid & 1;            // row half  (32 rows)
    const int wn = wid >> 1;           // col quarter (32 cols)
    const int r = lane >> 2, cc = lane & 3;
    const int tok0 = blockIdx.x * 64;
    const bool do_r = (wn == 0);

    float acc[2][4][4] = {};
    float racc[2][4]   = {};
    float4 rx[2][4];

    auto ldgx = [&](int kt, int b) {
        const float* xp = x + (size_t)tok0 * Dk + kt * 64;
#pragma unroll
        for (int p = 0; p < 4; p++) {
            int i = tid + p * 256, row = i >> 4, q = i & 15;
            rx[b][p] = *reinterpret_cast<const float4*>(xp + (size_t)row * Dk + q * 4);
        }
    };
    auto stsx = [&](int b, int st) {
        char* xb = xs0 + st * 9216;
#pragma unroll
        for (int p = 0; p < 4; p++) {
            int i = tid + p * 256, row = i >> 4, q = i & 15;
            float4 v = rx[b][p];
            __half2 h01 = __floats2half2_rn(v.x, v.y);
            __half2 h23 = __floats2half2_rn(v.z, v.w);
            uint2 u;
            u.x = *reinterpret_cast<uint32_t*>(&h01);
            u.y = *reinterpret_cast<uint32_t*>(&h23);
            *reinterpret_cast<uint2*>(xb + row * 144 + q * 8) = u;
        }
    };
    auto cpws = [&](int kt, int st) {
        const __half* wp = g_Awh + kt * 64;
        uint32_t wb = su + 22528 + st * 19584;
#pragma unroll
        for (int p = 0; p < 5; p++) {
            int i = tid + p * 256;
            if (i < 1088) {
                int row = i >> 3, q = i & 7;
                CP16(wb + row * 144 + q * 16, wp + (size_t)row * Dk + q * 8);
            }
        }
    };

    // prologue
    ldgx(0, 0);
    stsx(0, 0);
    ldgx(1, 1);
    cpws(0, 0); CP_COMMIT();
    cpws(1, 1); CP_COMMIT();

    for (int kt = 0; kt < NK1; kt++) {
        CP_WAIT(1);            // weight group for tile kt retired
        __syncthreads();       // publishes cp.async + previous stsx; protects reuse

        if (kt + 1 < NK1) stsx((kt + 1) & 1, (kt + 1) & 1);
        if (kt + 2 < NK1) { cpws(kt + 2, (kt + 2) % 3); ldgx(kt + 2, kt & 1); }
        CP_COMMIT();           // always commit to keep group accounting exact

        const uint32_t* xu = reinterpret_cast<const uint32_t*>(xs0 + (kt & 1) * 9216);
        const uint32_t* wu = reinterpret_cast<const uint32_t*>(ws0 + (kt % 3) * 19584);
#pragma unroll
        for (int ks = 0; ks < 4; ks++) {
            const int k0 = ks * 8;        // word offset of this k16 step
            uint32_t a[2][4];
#pragma unroll
            for (int mt = 0; mt < 2; mt++) {
                int b0 = (wm * 32 + mt * 16 + r) * S1 + k0 + cc;
                int b1 = (wm * 32 + mt * 16 + 8 + r) * S1 + k0 + cc;
                a[mt][0] = xu[b0];
                a[mt][1] = xu[b1];
                a[mt][2] = xu[b0 + 4];
                a[mt][3] = xu[b1 + 4];
            }
#pragma unroll
            for (int nt = 0; nt < 4; nt++) {
                int nb = (wn * 32 + nt * 8 + r) * S1 + k0 + cc;
                uint32_t b0 = wu[nb], b1 = wu[nb + 4];
                mma16(acc[0][nt], a[0][0], a[0][1], a[0][2], a[0][3], b0, b1);
                mma16(acc[1][nt], a[1][0], a[1][1], a[1][2], a[1][3], b0, b1);
            }
            if (do_r) {
                int nb = (128 + r) * S1 + k0 + cc;
                uint32_t b0 = wu[nb], b1 = wu[nb + 4];
                mma16(racc[0], a[0][0], a[0][1], a[0][2], a[0][3], b0, b1);
                mma16(racc[1], a[1][0], a[1][1], a[1][2], a[1][3], b0, b1);
            }
        }
    }

    // router logits -> slog
    if (do_r) {
#pragma unroll
        for (int mt = 0; mt < 2; mt++) {
            int tr = wm * 32 + mt * 16 + r;
            slog[tr * 8 + 2 * cc]           = racc[mt][0];
            slog[tr * 8 + 2 * cc + 1]       = racc[mt][1];
            slog[(tr + 8) * 8 + 2 * cc]     = racc[mt][2];
            slog[(tr + 8) * 8 + 2 * cc + 1] = racc[mt][3];
        }
    }
    __syncthreads();
    if (tid < 64) {   // softmax over 8 heads, fold H*SCALING = 16
        float l[8], m = -1e30f;
#pragma unroll
        for (int h = 0; h < 8; h++) {
            l[h] = slog[tid * 8 + h] + br[h];
            m = fmaxf(m, l[h]);
        }
        float s = 0.0f;
#pragma unroll
        for (int h = 0; h < 8; h++) { l[h] = __expf(l[h] - m); s += l[h]; }
        float inv = 16.0f / s;
#pragma unroll
        for (int h = 0; h < 8; h++) ssc[tid * 8 + h] = l[h] * inv;
    }
    __syncthreads();

    // scale + store wlow (fp16)
#pragma unroll
    for (int mt = 0; mt < 2; mt++) {
        int tr = wm * 32 + mt * 16 + r;
#pragma unroll
        for (int nt = 0; nt < 4; nt++) {
            int col  = wn * 32 + nt * 8 + 2 * cc;
            int head = (wn * 32 + nt * 8) >> 4;
            float s0 = ssc[tr * 8 + head];
            float s1 = ssc[(tr + 8) * 8 + head];
            *reinterpret_cast<__half2*>(&g_wlowh[(size_t)(tok0 + tr) * Kmid + col]) =
                __floats2half2_rn(acc[mt][nt][0] * s0, acc[mt][nt][1] * s0);
            *reinterpret_cast<__half2*>(&g_wlowh[(size_t)(tok0 + tr + 8) * Kmid + col]) =
                __floats2half2_rn(acc[mt][nt][2] * s1, acc[mt][nt][3] * s1);
        }
    }
}

// ---------------------------------------------------------------------------
// Kernel 2: out = wlow[8192,128] @ Bt[4096,128]^T  — persistent 148 CTAs
// Full K=128 halves resident (272B rows). A per m-block, B double-buffered.
// SMEM: A @0 (128*272=34816), B @34816 (2 x 34816) -> 104448
// ---------------------------------------------------------------------------
static constexpr int TB2     = 128 * 272;           // 34816 bytes per tile
static constexpr int K2_SMEM = 3 * TB2;             // 104448
static constexpr int NTILES  = (NTOK / 128) * (Oo / 128);   // 2048
static constexpr int GRID2   = 148;

__global__ __launch_bounds__(256, 1)
void k2_up(float* __restrict__ out) {
    extern __shared__ char sm[];
    const uint32_t su = (uint32_t)__cvta_generic_to_shared(sm);
    const int tid = threadIdx.x, wid = tid >> 5, lane = tid & 31;
    const int nw = wid & 1;            // col half  (64)
    const int mw = wid >> 1;           // row quarter (32)
    const int r = lane >> 2, cc = lane & 3;

    // copy one 128x128-half tile (row stride Kmid halves) into padded rows
    auto cp_tile = [&](const __half* src, uint32_t dst_off) {
#pragma unroll
        for (int p = 0; p < 8; p++) {
            int i = tid + p * 256;
            int row = i >> 4, q = i & 15;
            CP16(su + dst_off + row * 272 + q * 16,
                 src + (size_t)row * Kmid + q * 8);
        }
    };

    const int t0 = (blockIdx.x * NTILES) / GRID2;
    const int t1 = ((blockIdx.x + 1) * NTILES) / GRID2;
    int buf = 0, curmb = -1;

    for (int t = t0; t < t1; t++) {
        const int mb = t >> 5, nt = t & 31;
        const int m0 = mb * 128, nb = nt * 128;

        if (mb != curmb) {
            cp_tile(g_wlowh + (size_t)m0 * Kmid, 0);
            buf = 0;
            cp_tile(g_Bth + (size_t)nb * Kmid, (uint32_t)TB2);
            CP_COMMIT();
            curmb = mb;
        }
        CP_WAIT(0);
        __syncthreads();     // current A + B(buf) visible; prior reads of buf^1 done

        const bool nextsame = (t + 1 < t1) && (((t + 1) >> 5) == mb);
        if (nextsame) {      // prefetch next B overlaps compute + epilogue
            cp_tile(g_Bth + (size_t)((nt + 1) * 128) * Kmid,
                    (uint32_t)(TB2 + (buf ^ 1) * TB2));
            CP_COMMIT();
        }

        float acc[2][8][4] = {};
        const uint32_t* au = reinterpret_cast<const uint32_t*>(sm);
        const uint32_t* bu = reinterpret_cast<const uint32_t*>(sm + TB2 + buf * TB2);
#pragma unroll
        for (int ks = 0; ks < 8; ks++) {
            const int k0 = ks * 8;
            uint32_t a[2][4];
#pragma unroll
            for (int mt = 0; mt < 2; mt++) {
                int b0 = (mw * 32 + mt * 16 + r) * S2 + k0 + cc;
                int b1 = (mw * 32 + mt * 16 + 8 + r) * S2 + k0 + cc;
                a[mt][0] = au[b0];
                a[mt][1] = au[b1];
                a[mt][2] = au[b0 + 4];
                a[mt][3] = au[b1 + 4];
            }
#pragma unroll
            for (int j = 0; j < 8; j++) {
                int nbx = (nw * 64 + j * 8 + r) * S2 + k0 + cc;
                uint32_t b0 = bu[nbx], b1 = bu[nbx + 4];
                mma16(acc[0][j], a[0][0], a[0][1], a[0][2], a[0][3], b0, b1);
                mma16(acc[1][j], a[1][0], a[1][1], a[1][2], a[1][3], b0, b1);
            }
        }

        // epilogue: STG fp32 out (overlaps with in-flight prefetch)
#pragma unroll
        for (int mt = 0; mt < 2; mt++) {
            int row = m0 + mw * 32 + mt * 16 + r;
#pragma unroll
            for (int j = 0; j < 8; j++) {
                int col = nb + nw * 64 + j * 8 + 2 * cc;
                *reinterpret_cast<float2*>(&out[(size_t)row * Oo + col]) =
                    make_float2(acc[mt][j][0], acc[mt][j][1]);
                *reinterpret_cast<float2*>(&out[(size_t)(row + 8) * Oo + col]) =
                    make_float2(acc[mt][j][2], acc[mt][j][3]);
            }
        }
        if (nextsame) buf ^= 1;
    }
}

// ---------------------------------------------------------------------------
extern "C" void kernel_launch(void* const* d_in, const int* in_sizes, int n_in,
                              void* d_out, int out_size) {
    const float* x  = (const float*)d_in[0];
    const float* A  = (const float*)d_in[1];
    const float* Bm = (const float*)d_in[2];
    const float* Wr = (const float*)d_in[3];
    const float* br = (const float*)d_in[4];
    float* out = (float*)d_out;

    cudaFuncSetAttribute(k1_low, cudaFuncAttributeMaxDynamicSharedMemorySize, K1_SMEM);
    cudaFuncSetAttribute(k2_up,  cudaFuncAttributeMaxDynamicSharedMemorySize, K2_SMEM);

    prep<<<(136 * Dk + 255) / 256, 256>>>(A, Wr, Bm);
    k1_low<<<NTOK / 64, 256, K1_SMEM>>>(x, br);
    k2_up<<<GRID2, 256, K2_SMEM>>>(out);
}

// round 10
// speedup vs baseline: 1.6501x; 1.0106x over previous
#include <cuda_runtime.h>
#include <cuda_fp16.h>
#include <stdint.h>

static constexpr int Dk   = 4096;
static constexpr int Oo   = 4096;
static constexpr int Kmid = 128;
static constexpr int NTOK = 8192;
static constexpr int NK1  = 64;       // K-tiles in kernel 1 (4096/64)

// Scratch (device globals — no allocation allowed)
__device__ __half g_wlowh[NTOK * Kmid];   // 2 MB   score-weighted low acts (fp16)
__device__ __half g_Awh[136 * Dk];        // 1.1 MB [A(128 rows) ; Wr(8 rows)] fp16
__device__ __half g_Bth[Oo * Kmid];       // 1 MB   Bt[o][h*16+rr] fp16

// ---------------------------------------------------------------------------
// helpers
// ---------------------------------------------------------------------------
__device__ __forceinline__ void mma16(float* c, uint32_t a0, uint32_t a1,
                                      uint32_t a2, uint32_t a3,
                                      uint32_t b0, uint32_t b1) {
    asm volatile(
        "mma.sync.aligned.m16n8k16.row.col.f32.f16.f16.f32 "
        "{%0,%1,%2,%3}, {%4,%5,%6,%7}, {%8,%9}, {%0,%1,%2,%3};\n"
        : "+f"(c[0]), "+f"(c[1]), "+f"(c[2]), "+f"(c[3])
        : "r"(a0), "r"(a1), "r"(a2), "r"(a3), "r"(b0), "r"(b1));
}
#define LDSM4(R0, R1, R2, R3, ADDR) \
    asm volatile("ldmatrix.sync.aligned.m8n8.x4.shared.b16 {%0,%1,%2,%3}, [%4];" \
        : "=r"(R0), "=r"(R1), "=r"(R2), "=r"(R3) : "r"(ADDR))
#define LDSM2(R0, R1, ADDR) \
    asm volatile("ldmatrix.sync.aligned.m8n8.x2.shared.b16 {%0,%1}, [%2];" \
        : "=r"(R0), "=r"(R1) : "r"(ADDR))
#define CP16(dst_u32, src_ptr) \
    asm volatile("cp.async.cg.shared.global [%0], [%1], 16;\n" :: "r"(dst_u32), "l"(src_ptr))
#define CP_COMMIT() asm volatile("cp.async.commit_group;\n" ::: "memory")
#define CP_WAIT(N)  asm volatile("cp.async.wait_group %0;\n" :: "n"(N) : "memory")

// ---------------------------------------------------------------------------
// Kernel 0: convert weights to fp16 scratch
// ---------------------------------------------------------------------------
__global__ void prep(const float* __restrict__ A, const float* __restrict__ Wr,
                     const float* __restrict__ Bm) {
    int idx = blockIdx.x * 256 + threadIdx.x;
    if (idx < 136 * Dk) {
        int row = idx >> 12, col = idx & (Dk - 1);
        float v = (row < 128) ? A[(size_t)row * Dk + col]
                              : Wr[(size_t)(row - 128) * Dk + col];
        g_Awh[idx] = __float2half_rn(v);
    }
    if (idx < Oo * Kmid) {
        int o = idx >> 7, k = idx & 127;
        g_Bth[idx] = __float2half_rn(
            Bm[((size_t)((k >> 4) * Oo + o)) * 16 + (k & 15)]);
    }
}

// ---------------------------------------------------------------------------
// Kernel 1: low = x @ [A;Wr]^T  (BM=64, BN=128 + 8 router, BK=64 halves)
// fp16 mma.sync + ldmatrix; 3-stage cp.async weight ring; 2-stage x path.
// SMEM: slog@0(2K) ssc@2K(2K) xs@4096 (2 x 64*144) ws@22528 (3 x 136*144)
// ---------------------------------------------------------------------------
static constexpr int K1_SMEM = 22528 + 3 * 19584;   // 81280

__global__ __launch_bounds__(256, 1)
void k1_low(const float* __restrict__ x, const float* __restrict__ br) {
    extern __shared__ char sm[];
    const uint32_t su = (uint32_t)__cvta_generic_to_shared(sm);
    float* slog = (float*)(sm);
    float* ssc  = (float*)(sm + 2048);

    const int tid = threadIdx.x, wid = tid >> 5, lane = tid & 31;
    const int wm = wid & 1;            // row half  (32 rows)
    const int wn = wid >> 1;           // col quarter (32 cols)
    const int r = lane >> 2, cc = lane & 3;
    const int tok0 = blockIdx.x * 64;
    const bool do_r = (wn == 0);

    // ldmatrix per-lane byte offsets (within a stage buffer)
    const int aoff0 = (wm * 32 + (lane & 15)) * 144 + ((lane >> 4) << 4);
    const int aoff1 = aoff0 + 16 * 144;
    const int boff0 = (wn * 32 + (lane & 7) + ((lane >> 4) << 3)) * 144
                      + (((lane >> 3) & 1) << 4);
    const int boff1 = boff0 + 16 * 144;
    const int roff  = (128 + (lane & 7)) * 144 + (((lane >> 3) & 1) << 4);

    float acc[2][4][4] = {};
    float racc[2][4]   = {};
    float4 rx[2][4];

    auto ldgx = [&](int kt, int b) {
        const float* xp = x + (size_t)tok0 * Dk + kt * 64;
#pragma unroll
        for (int p = 0; p < 4; p++) {
            int i = tid + p * 256, row = i >> 4, q = i & 15;
            rx[b][p] = *reinterpret_cast<const float4*>(xp + (size_t)row * Dk + q * 4);
        }
    };
    auto stsx = [&](int b, int st) {
        char* xb = sm + 4096 + st * 9216;
#pragma unroll
        for (int p = 0; p < 4; p++) {
            int i = tid + p * 256, row = i >> 4, q = i & 15;
            float4 v = rx[b][p];
            __half2 h01 = __floats2half2_rn(v.x, v.y);
            __half2 h23 = __floats2half2_rn(v.z, v.w);
            uint2 u;
            u.x = *reinterpret_cast<uint32_t*>(&h01);
            u.y = *reinterpret_cast<uint32_t*>(&h23);
            *reinterpret_cast<uint2*>(xb + row * 144 + q * 8) = u;
        }
    };
    auto cpws = [&](int kt, int st) {
        const __half* wp = g_Awh + kt * 64;
        uint32_t wb = su + 22528 + st * 19584;
#pragma unroll
        for (int p = 0; p < 5; p++) {
            int i = tid + p * 256;
            if (i < 1088) {
                int row = i >> 3, q = i & 7;
                CP16(wb + row * 144 + q * 16, wp + (size_t)row * Dk + q * 8);
            }
        }
    };

    // prologue
    ldgx(0, 0);
    stsx(0, 0);
    ldgx(1, 1);
    cpws(0, 0); CP_COMMIT();
    cpws(1, 1); CP_COMMIT();

    for (int kt = 0; kt < NK1; kt++) {
        CP_WAIT(1);            // weight group for tile kt retired
        __syncthreads();       // publishes cp.async + previous stsx; protects reuse

        if (kt + 1 < NK1) stsx((kt + 1) & 1, (kt + 1) & 1);
        if (kt + 2 < NK1) { cpws(kt + 2, (kt + 2) % 3); ldgx(kt + 2, kt & 1); }
        CP_COMMIT();           // always commit to keep group accounting exact

        const uint32_t xb = su + 4096 + (kt & 1) * 9216;
        const uint32_t wb = su + 22528 + (kt % 3) * 19584;
#pragma unroll
        for (int ks = 0; ks < 4; ks++) {
            const int kb = ks * 32;   // byte advance per k16 step
            uint32_t a[2][4];
            LDSM4(a[0][0], a[0][1], a[0][2], a[0][3], xb + aoff0 + kb);
            LDSM4(a[1][0], a[1][1], a[1][2], a[1][3], xb + aoff1 + kb);
#pragma unroll
            for (int p = 0; p < 2; p++) {
                uint32_t b0, b1, b2, b3;
                LDSM4(b0, b1, b2, b3, wb + ((p == 0) ? boff0 : boff1) + kb);
                mma16(acc[0][2 * p],     a[0][0], a[0][1], a[0][2], a[0][3], b0, b1);
                mma16(acc[1][2 * p],     a[1][0], a[1][1], a[1][2], a[1][3], b0, b1);
                mma16(acc[0][2 * p + 1], a[0][0], a[0][1], a[0][2], a[0][3], b2, b3);
                mma16(acc[1][2 * p + 1], a[1][0], a[1][1], a[1][2], a[1][3], b2, b3);
            }
            if (do_r) {
                uint32_t b0, b1;
                LDSM2(b0, b1, wb + roff + kb);
                mma16(racc[0], a[0][0], a[0][1], a[0][2], a[0][3], b0, b1);
                mma16(racc[1], a[1][0], a[1][1], a[1][2], a[1][3], b0, b1);
            }
        }
    }

    // router logits -> slog
    if (do_r) {
#pragma unroll
        for (int mt = 0; mt < 2; mt++) {
            int tr = wm * 32 + mt * 16 + r;
            slog[tr * 8 + 2 * cc]           = racc[mt][0];
            slog[tr * 8 + 2 * cc + 1]       = racc[mt][1];
            slog[(tr + 8) * 8 + 2 * cc]     = racc[mt][2];
            slog[(tr + 8) * 8 + 2 * cc + 1] = racc[mt][3];
        }
    }
    __syncthreads();
    if (tid < 64) {   // softmax over 8 heads, fold H*SCALING = 16
        float l[8], m = -1e30f;
#pragma unroll
        for (int h = 0; h < 8; h++) {
            l[h] = slog[tid * 8 + h] + br[h];
            m = fmaxf(m, l[h]);
        }
        float s = 0.0f;
#pragma unroll
        for (int h = 0; h < 8; h++) { l[h] = __expf(l[h] - m); s += l[h]; }
        float inv = 16.0f / s;
#pragma unroll
        for (int h = 0; h < 8; h++) ssc[tid * 8 + h] = l[h] * inv;
    }
    __syncthreads();

    // scale + store wlow (fp16)
#pragma unroll
    for (int mt = 0; mt < 2; mt++) {
        int tr = wm * 32 + mt * 16 + r;
#pragma unroll
        for (int nt = 0; nt < 4; nt++) {
            int col  = wn * 32 + nt * 8 + 2 * cc;
            int head = (wn * 32 + nt * 8) >> 4;
            float s0 = ssc[tr * 8 + head];
            float s1 = ssc[(tr + 8) * 8 + head];
            *reinterpret_cast<__half2*>(&g_wlowh[(size_t)(tok0 + tr) * Kmid + col]) =
                __floats2half2_rn(acc[mt][nt][0] * s0, acc[mt][nt][1] * s0);
            *reinterpret_cast<__half2*>(&g_wlowh[(size_t)(tok0 + tr + 8) * Kmid + col]) =
                __floats2half2_rn(acc[mt][nt][2] * s1, acc[mt][nt][3] * s1);
        }
    }
}

// ---------------------------------------------------------------------------
// Kernel 2: out = wlow[8192,128] @ Bt[4096,128]^T — persistent, 2 CTAs/SM
// Full K=128 halves resident (272B rows). A per m-block, B double-buffered.
// SMEM: A @0 (34816), B @34816 (2 x 34816) -> 104448; grid 296 (occ 2)
// RACE FIX vs R7: barrier BEFORE overwriting A/B at an m-block change.
// ---------------------------------------------------------------------------
static constexpr int TB2     = 128 * 272;           // 34816 bytes per tile
static constexpr int K2_SMEM = 3 * TB2;             // 104448
static constexpr int NTILES  = (NTOK / 128) * (Oo / 128);   // 2048
static constexpr int GRID2   = 296;

__global__ __launch_bounds__(256, 2)
void k2_up(float* __restrict__ out) {
    extern __shared__ char sm[];
    const uint32_t su = (uint32_t)__cvta_generic_to_shared(sm);
    const int tid = threadIdx.x, wid = tid >> 5, lane = tid & 31;
    const int nw = wid & 1;            // col half  (64)
    const int mw = wid >> 1;           // row quarter (32)
    const int r = lane >> 2, cc = lane & 3;

    // ldmatrix per-lane byte offsets
    const int aoff0 = (mw * 32 + (lane & 15)) * 272 + ((lane >> 4) << 4);
    const int aoff1 = aoff0 + 16 * 272;
    int boff[4];
#pragma unroll
    for (int p = 0; p < 4; p++)
        boff[p] = (nw * 64 + p * 16 + (lane & 7) + ((lane >> 4) << 3)) * 272
                  + (((lane >> 3) & 1) << 4);

    // copy one 128x128-half tile (row stride Kmid halves) into padded rows
    auto cp_tile = [&](const __half* src, uint32_t dst_off) {
#pragma unroll
        for (int p = 0; p < 8; p++) {
            int i = tid + p * 256;
            int row = i >> 4, q = i & 15;
            CP16(su + dst_off + row * 272 + q * 16,
                 src + (size_t)row * Kmid + q * 8);
        }
    };

    const int t0 = (blockIdx.x * NTILES) / GRID2;
    const int t1 = ((blockIdx.x + 1) * NTILES) / GRID2;
    int buf = 0, curmb = -1;

    for (int t = t0; t < t1; t++) {
        const int mb = t >> 5, nt = t & 31;
        const int m0 = mb * 128, nb = nt * 128;

        if (mb != curmb) {
            if (curmb >= 0) __syncthreads();   // RACE FIX: all warps done reading
            cp_tile(g_wlowh + (size_t)m0 * Kmid, 0);
            buf = 0;
            cp_tile(g_Bth + (size_t)nb * Kmid, (uint32_t)TB2);
            CP_COMMIT();
            curmb = mb;
        }
        CP_WAIT(0);
        __syncthreads();     // current A + B(buf) visible; prior reads of buf^1 done

        const bool nextsame = (t + 1 < t1) && (((t + 1) >> 5) == mb);
        if (nextsame) {      // prefetch next B overlaps compute + epilogue
            cp_tile(g_Bth + (size_t)((nt + 1) * 128) * Kmid,
                    (uint32_t)(TB2 + (buf ^ 1) * TB2));
            CP_COMMIT();
        }

        float acc[2][8][4] = {};
        const uint32_t ab = su;
        const uint32_t bb = su + TB2 + buf * TB2;
#pragma unroll
        for (int ks = 0; ks < 8; ks++) {
            const int kb = ks * 32;
            uint32_t a[2][4];
            LDSM4(a[0][0], a[0][1], a[0][2], a[0][3], ab + aoff0 + kb);
            LDSM4(a[1][0], a[1][1], a[1][2], a[1][3], ab + aoff1 + kb);
#pragma unroll
            for (int p = 0; p < 4; p++) {
                uint32_t b0, b1, b2, b3;
                LDSM4(b0, b1, b2, b3, bb + boff[p] + kb);
                mma16(acc[0][2 * p],     a[0][0], a[0][1], a[0][2], a[0][3], b0, b1);
                mma16(acc[1][2 * p],     a[1][0], a[1][1], a[1][2], a[1][3], b0, b1);
                mma16(acc[0][2 * p + 1], a[0][0], a[0][1], a[0][2], a[0][3], b2, b3);
                mma16(acc[1][2 * p + 1], a[1][0], a[1][1], a[1][2], a[1][3], b2, b3);
            }
        }

        // epilogue: STG fp32 out (overlaps with in-flight prefetch)
#pragma unroll
        for (int mt = 0; mt < 2; mt++) {
            int row = m0 + mw * 32 + mt * 16 + r;
#pragma unroll
            for (int j = 0; j < 8; j++) {
                int col = nb + nw * 64 + j * 8 + 2 * cc;
                *reinterpret_cast<float2*>(&out[(size_t)row * Oo + col]) =
                    make_float2(acc[mt][j][0], acc[mt][j][1]);
                *reinterpret_cast<float2*>(&out[(size_t)(row + 8) * Oo + col]) =
                    make_float2(acc[mt][j][2], acc[mt][j][3]);
            }
        }
        if (nextsame) buf ^= 1;
    }
}

// ---------------------------------------------------------------------------
extern "C" void kernel_launch(void* const* d_in, const int* in_sizes, int n_in,
                              void* d_out, int out_size) {
    const float* x  = (const float*)d_in[0];
    const float* A  = (const float*)d_in[1];
    const float* Bm = (const float*)d_in[2];
    const float* Wr = (const float*)d_in[3];
    const float* br = (const float*)d_in[4];
    float* out = (float*)d_out;

    cudaFuncSetAttribute(k1_low, cudaFuncAttributeMaxDynamicSharedMemorySize, K1_SMEM);
    cudaFuncSetAttribute(k2_up,  cudaFuncAttributeMaxDynamicSharedMemorySize, K2_SMEM);

    prep<<<(136 * Dk + 255) / 256, 256>>>(A, Wr, Bm);
    k1_low<<<NTOK / 64, 256, K1_SMEM>>>(x, br);
    k2_up<<<GRID2, 256, K2_SMEM>>>(out);
}